// round 9
// baseline (speedup 1.0000x reference)
#include <cuda_runtime.h>
#include <cuda_bf16.h>
#include <math.h>

#define NB 8
#define NN 2048
#define ND 128
#define NT 16

// ---------------- scratch (allocation-free device globals) ----------------
__device__ __align__(16) unsigned short g_h1hi[NB * NN * ND];  // bf16 hi of h1 [b,n,d]
__device__ __align__(16) unsigned short g_h1lo[NB * NN * ND];  // bf16 lo (residual)
__device__ __align__(16) float g_rinv[NB * NN];
__device__ __align__(16) float g_agg[NB * NN * ND];            // inter-layer fp32 (pre-relu)

// ---------------- helpers ----------------
__device__ __forceinline__ unsigned smem_u32(const void* p) {
    unsigned a;
    asm("{ .reg .u64 t; cvta.to.shared.u64 t, %1; cvt.u32.u64 %0, t; }" : "=r"(a) : "l"(p));
    return a;
}
__device__ __forceinline__ void ldmx4(unsigned* r, unsigned a) {
    asm volatile("ldmatrix.sync.aligned.m8n8.x4.shared.b16 {%0,%1,%2,%3}, [%4];"
        : "=r"(r[0]), "=r"(r[1]), "=r"(r[2]), "=r"(r[3]) : "r"(a));
}
__device__ __forceinline__ void ldmx4t(unsigned* r, unsigned a) {
    asm volatile("ldmatrix.sync.aligned.m8n8.x4.trans.shared.b16 {%0,%1,%2,%3}, [%4];"
        : "=r"(r[0]), "=r"(r[1]), "=r"(r[2]), "=r"(r[3]) : "r"(a));
}
__device__ __forceinline__ void mma_bf16(float* d, const unsigned* a,
                                         unsigned b0, unsigned b1) {
    asm volatile("mma.sync.aligned.m16n8k16.row.col.f32.bf16.bf16.f32 "
        "{%0,%1,%2,%3},{%4,%5,%6,%7},{%8,%9},{%0,%1,%2,%3};"
        : "+f"(d[0]), "+f"(d[1]), "+f"(d[2]), "+f"(d[3])
        : "r"(a[0]), "r"(a[1]), "r"(a[2]), "r"(a[3]), "r"(b0), "r"(b1));
}
__device__ __forceinline__ unsigned pack_bf16(float lo, float hi) {
    unsigned r;
    asm("cvt.rn.bf16x2.f32 %0, %1, %2;" : "=r"(r) : "f"(hi), "f"(lo));
    return r;
}
#define CP_ASYNC16(dst, src) \
    asm volatile("cp.async.cg.shared.global [%0], [%1], 16;" \
        :: "r"((unsigned)(dst)), "l"(src) : "memory")
#define CP_COMMIT() asm volatile("cp.async.commit_group;" ::: "memory")
#define CP_WAIT0()  asm volatile("cp.async.wait_group 0;" ::: "memory")

// ============================================================
// klinear: h1 = relu?(hin) @ W + b ; rinv = 1/max(||h1||,eps)
// relu is folded into the input read (aggregation relu of previous layer).
// 64-row tiles, 256 threads; each warp owns 8 rows x 128 cols.
// ============================================================
__global__ __launch_bounds__(256) void klinear(
    const float* __restrict__ xin, const float* __restrict__ W,
    const float* __restrict__ bias, int use_gagg)
{
    __shared__ float sH[64][128];
    const float* hin = use_gagg ? (const float*)g_agg : xin;
    int tid = threadIdx.x;
    size_t row0 = (size_t)blockIdx.x * 64;

#pragma unroll
    for (int i = tid; i < 64 * 32; i += 256) {
        int r = i >> 5, kb = i & 31;
        float4 v = *(const float4*)(hin + (row0 + r) * (size_t)ND + 4 * kb);
        if (use_gagg) {
            v.x = fmaxf(v.x, 0.0f); v.y = fmaxf(v.y, 0.0f);
            v.z = fmaxf(v.z, 0.0f); v.w = fmaxf(v.w, 0.0f);
        }
        *(float4*)&sH[r][4 * kb] = v;
    }
    __syncthreads();

    int wy = tid >> 5, tx = tid & 31;   // warp wy: rows 8*wy..8*wy+7
    float acc[8][4];
    {
        float4 bv = *(const float4*)(bias + 4 * tx);
#pragma unroll
        for (int i = 0; i < 8; i++) {
            acc[i][0] = bv.x; acc[i][1] = bv.y; acc[i][2] = bv.z; acc[i][3] = bv.w;
        }
    }
#pragma unroll 4
    for (int k = 0; k < ND; k++) {
        float4 wv = *(const float4*)(W + (size_t)k * ND + 4 * tx);
#pragma unroll
        for (int i = 0; i < 8; i++) {
            float hr = sH[8 * wy + i][k];
            acc[i][0] = fmaf(hr, wv.x, acc[i][0]);
            acc[i][1] = fmaf(hr, wv.y, acc[i][1]);
            acc[i][2] = fmaf(hr, wv.z, acc[i][2]);
            acc[i][3] = fmaf(hr, wv.w, acc[i][3]);
        }
    }

#pragma unroll
    for (int i = 0; i < 8; i++) {
        float ss = acc[i][0] * acc[i][0] + acc[i][1] * acc[i][1]
                 + acc[i][2] * acc[i][2] + acc[i][3] * acc[i][3];
#pragma unroll
        for (int o = 16; o > 0; o >>= 1) ss += __shfl_xor_sync(0xffffffffu, ss, o);
        float ri = 1.0f / fmaxf(sqrtf(ss), 1e-12f);
        size_t row = row0 + 8 * wy + i;
        unsigned short ush[4], usl[4];
#pragma unroll
        for (int c2 = 0; c2 < 4; c2++) {
            __nv_bfloat16 hb = __float2bfloat16(acc[i][c2]);
            float res = acc[i][c2] - __bfloat162float(hb);
            ush[c2] = __bfloat16_as_ushort(hb);
            usl[c2] = __bfloat16_as_ushort(__float2bfloat16(res));
        }
        uint2 ph = make_uint2(ush[0] | ((unsigned)ush[1] << 16), ush[2] | ((unsigned)ush[3] << 16));
        uint2 pl = make_uint2(usl[0] | ((unsigned)usl[1] << 16), usl[2] | ((unsigned)usl[3] << 16));
        *(uint2*)(g_h1hi + row * ND + 4 * tx) = ph;
        *(uint2*)(g_h1lo + row * ND + 4 * tx) = pl;
        if (tx == 0) g_rinv[row] = ri;
    }
}

// ============================================================
// kaggr_mma: out[p,:] = sum_q ew[p,q]*rp*rq*(h1_p . h1_q) * h1[q,:]
// mma.sync bf16 split, pass-major ordering (dep distance 8), cp.async dbuf.
// ============================================================
#define SROWB 272                 // bytes per smem row (128+8 halfs)
#define TILEB 34816               // one 128-row tile (hi or lo)
#define OFF_HPH 0
#define OFF_HPL TILEB
#define OFF_HQ0 (2 * TILEB)       // buffer 0: hi at +0, lo at +TILEB
#define OFF_HQ1 (4 * TILEB)       // buffer 1
#define OFF_RQ  (6 * TILEB)       // 2 x 512B
#define SM_TOT  (6 * TILEB + 1024)

__global__ __launch_bounds__(256) void kaggr_mma(
    const float* __restrict__ ew, float* __restrict__ dout, int is_last)
{
    extern __shared__ char sm[];
    unsigned sb = smem_u32(sm);
    int tid = threadIdx.x, wid = tid >> 5, lane = tid & 31;
    int b = blockIdx.y, p0 = blockIdx.x * 128;

    const unsigned short* hh = g_h1hi + (size_t)b * NN * ND;
    const unsigned short* hl = g_h1lo + (size_t)b * NN * ND;
    const float* ewb = ew + (size_t)b * NN * NN;
    const float* rb = g_rinv + (size_t)b * NN;
    float* ob = (is_last ? dout : (float*)g_agg) + (size_t)b * NN * ND;

    // persistent Hp hi/lo tile
#pragma unroll
    for (int f = tid; f < 2048; f += 256) {
        int r = f >> 4, ch = f & 15;
        *(uint4*)(sm + OFF_HPH + r * SROWB + ch * 16) =
            *(const uint4*)(hh + (size_t)(p0 + r) * ND + ch * 8);
        *(uint4*)(sm + OFF_HPL + r * SROWB + ch * 16) =
            *(const uint4*)(hl + (size_t)(p0 + r) * ND + ch * 8);
    }

    int g = lane >> 2, c = lane & 3;
    int mrow = wid * 16;
    float rp0 = rb[p0 + mrow + g];
    float rp1 = rb[p0 + mrow + g + 8];
    const float* ew0 = ewb + (size_t)(p0 + mrow + g) * NN;
    const float* ew1 = ewb + (size_t)(p0 + mrow + g + 8) * NN;

    int grp = lane >> 3, wi = lane & 7;
    unsigned offA = (unsigned)((mrow + wi + (grp & 1) * 8) * SROWB + (grp >> 1) * 16);
    unsigned offB = (unsigned)((wi + (grp >> 1) * 8) * SROWB + (grp & 1) * 16);
    unsigned offT = (unsigned)((wi + (grp & 1) * 8) * SROWB + (grp >> 1) * 16);

    float o[16][4];
#pragma unroll
    for (int j = 0; j < 16; j++)
#pragma unroll
        for (int k = 0; k < 4; k++) o[j][k] = 0.0f;

    auto issue_tile = [&](int t, unsigned bufoff) {
        int q0 = t << 7;
#pragma unroll
        for (int f = tid; f < 2048; f += 256) {
            int r = f >> 4, ch = f & 15;
            CP_ASYNC16(sb + bufoff + r * SROWB + ch * 16,
                       hh + (size_t)(q0 + r) * ND + ch * 8);
            CP_ASYNC16(sb + bufoff + TILEB + r * SROWB + ch * 16,
                       hl + (size_t)(q0 + r) * ND + ch * 8);
        }
        if (tid < 32) CP_ASYNC16(sb + OFF_RQ + ((unsigned)(t & 1) << 9) + tid * 16,
                                 rb + q0 + tid * 4);
        CP_COMMIT();
    };

    issue_tile(0, OFF_HQ0);

    for (int t = 0; t < NT; t++) {
        unsigned bufoff = (t & 1) ? OFF_HQ1 : OFF_HQ0;
        CP_WAIT0();
        __syncthreads();
        if (t + 1 < NT) issue_tile(t + 1, (t & 1) ? OFF_HQ0 : OFF_HQ1);

        int q0 = t << 7;
        const float* s_rq = (const float*)(sm + OFF_RQ + ((unsigned)(t & 1) << 9));

#pragma unroll
        for (int nh = 0; nh < 2; nh++) {
            // EW prefetch for this n-half (hidden under GEMM1 MMAs)
            float2 eq0[8], eq1[8];
#pragma unroll
            for (int tl = 0; tl < 8; tl++) {
                int col = q0 + (nh * 8 + tl) * 8 + 2 * c;
                eq0[tl] = *(const float2*)(ew0 + col);
                eq1[tl] = *(const float2*)(ew1 + col);
            }

            // ---- GEMM1: S-half = Hp . Hq^T (pass-major: dep distance 8) ----
            float s[8][4];
#pragma unroll
            for (int j = 0; j < 8; j++)
#pragma unroll
                for (int k = 0; k < 4; k++) s[j][k] = 0.0f;

#pragma unroll
            for (int kk = 0; kk < 8; kk++) {
                unsigned ah[4], al[4];
                ldmx4(ah, sb + OFF_HPH + offA + kk * 32);
                ldmx4(al, sb + OFF_HPL + offA + kk * 32);
                unsigned bh[4][4], bl[4][4];
#pragma unroll
                for (int np = 0; np < 4; np++) {
                    unsigned nb = bufoff + (unsigned)((nh * 4 + np) * 16 * SROWB);
                    ldmx4(bh[np], sb + nb + offB + kk * 32);
                    ldmx4(bl[np], sb + nb + TILEB + offB + kk * 32);
                }
#pragma unroll
                for (int np = 0; np < 4; np++) {   // pass 1: hi*hi
                    mma_bf16(s[2 * np], ah, bh[np][0], bh[np][1]);
                    mma_bf16(s[2 * np + 1], ah, bh[np][2], bh[np][3]);
                }
#pragma unroll
                for (int np = 0; np < 4; np++) {   // pass 2: lo*hi
                    mma_bf16(s[2 * np], al, bh[np][0], bh[np][1]);
                    mma_bf16(s[2 * np + 1], al, bh[np][2], bh[np][3]);
                }
#pragma unroll
                for (int np = 0; np < 4; np++) {   // pass 3: hi*lo
                    mma_bf16(s[2 * np], ah, bl[np][0], bl[np][1]);
                    mma_bf16(s[2 * np + 1], ah, bl[np][2], bl[np][3]);
                }
            }

            // ---- scale + bf16 split -> A fragments (4 kk groups) ----
            unsigned SAh[4][4], SAl[4][4];
#pragma unroll
            for (int tl = 0; tl < 8; tl++) {
                int col = (nh * 8 + tl) * 8 + 2 * c;
                float2 rq2 = *(const float2*)&s_rq[col];
                float2 e0 = eq0[tl];
                float2 e1 = eq1[tl];
                float v0 = s[tl][0] * (rp0 * rq2.x * e0.x);
                float v1 = s[tl][1] * (rp0 * rq2.y * e0.y);
                float v2 = s[tl][2] * (rp1 * rq2.x * e1.x);
                float v3 = s[tl][3] * (rp1 * rq2.y * e1.y);
                __nv_bfloat16 h0 = __float2bfloat16(v0);
                __nv_bfloat16 h1v = __float2bfloat16(v1);
                __nv_bfloat16 h2 = __float2bfloat16(v2);
                __nv_bfloat16 h3 = __float2bfloat16(v3);
                float r0v = v0 - __bfloat162float(h0);
                float r1v = v1 - __bfloat162float(h1v);
                float r2v = v2 - __bfloat162float(h2);
                float r3v = v3 - __bfloat162float(h3);
                int kl = tl >> 1, sl = (tl & 1) * 2;
                SAh[kl][sl]     = (unsigned)__bfloat16_as_ushort(h0)
                                | ((unsigned)__bfloat16_as_ushort(h1v) << 16);
                SAh[kl][sl + 1] = (unsigned)__bfloat16_as_ushort(h2)
                                | ((unsigned)__bfloat16_as_ushort(h3) << 16);
                SAl[kl][sl]     = pack_bf16(r0v, r1v);
                SAl[kl][sl + 1] = pack_bf16(r2v, r3v);
            }

            // ---- GEMM2: o += S_half x Hq (pass-major over np groups of 4) ----
#pragma unroll
            for (int kl = 0; kl < 4; kl++) {
                unsigned kb = bufoff + (unsigned)((nh * 4 + kl) * 16 * SROWB);
#pragma unroll
                for (int npg = 0; npg < 2; npg++) {
                    unsigned bh[4][4], bl[4][4];
#pragma unroll
                    for (int np = 0; np < 4; np++) {
                        ldmx4t(bh[np], sb + kb + offT + (npg * 4 + np) * 32);
                        ldmx4t(bl[np], sb + kb + TILEB + offT + (npg * 4 + np) * 32);
                    }
#pragma unroll
                    for (int np = 0; np < 4; np++) {   // pass 1: SAh * bh
                        int j = (npg * 4 + np) * 2;
                        mma_bf16(o[j], SAh[kl], bh[np][0], bh[np][1]);
                        mma_bf16(o[j + 1], SAh[kl], bh[np][2], bh[np][3]);
                    }
#pragma unroll
                    for (int np = 0; np < 4; np++) {   // pass 2: SAl * bh
                        int j = (npg * 4 + np) * 2;
                        mma_bf16(o[j], SAl[kl], bh[np][0], bh[np][1]);
                        mma_bf16(o[j + 1], SAl[kl], bh[np][2], bh[np][3]);
                    }
#pragma unroll
                    for (int np = 0; np < 4; np++) {   // pass 3: SAh * bl
                        int j = (npg * 4 + np) * 2;
                        mma_bf16(o[j], SAh[kl], bl[np][0], bl[np][1]);
                        mma_bf16(o[j + 1], SAh[kl], bl[np][2], bl[np][3]);
                    }
                }
            }
        }
    }

    // ---- epilogue: fragment-layout stores (relu handled by next klinear) ----
    float* r0p = ob + (size_t)(p0 + mrow + g) * ND;
    float* r1p = ob + (size_t)(p0 + mrow + g + 8) * ND;
#pragma unroll
    for (int j = 0; j < 16; j++) {
        *(float2*)(r0p + 8 * j + 2 * c) = make_float2(o[j][0], o[j][1]);
        *(float2*)(r1p + 8 * j + 2 * c) = make_float2(o[j][2], o[j][3]);
    }
}

// ============================================================
extern "C" void kernel_launch(void* const* d_in, const int* in_sizes, int n_in,
                              void* d_out, int out_size)
{
    const float* x  = (const float*)d_in[0];
    const float* ew = (const float*)d_in[1];
    const float* W[3]    = {(const float*)d_in[2], (const float*)d_in[4], (const float*)d_in[6]};
    const float* bias[3] = {(const float*)d_in[3], (const float*)d_in[5], (const float*)d_in[7]};
    float* out = (float*)d_out;

    cudaFuncSetAttribute(kaggr_mma, cudaFuncAttributeMaxDynamicSharedMemorySize, SM_TOT);

    dim3 gA(NB * NN / 64);
    dim3 gB(NN / 128, NB);

    for (int layer = 0; layer < 3; layer++) {
        klinear<<<gA, 256>>>(x, W[layer], bias[layer], layer > 0 ? 1 : 0);
        kaggr_mma<<<gB, 256, SM_TOT>>>(ew, out, layer == 2 ? 1 : 0);
    }
}